// round 1
// baseline (speedup 1.0000x reference)
#include <cuda_runtime.h>

#define NN 10000
#define RR 100
#define EE 5000
#define NEDGE (RR * EE)

// ---------------- scratch (device globals; no allocations) ----------------
__device__ int   g_deg[RR * NN];          // edges per (relation, dst)
__device__ float g_x[NN * 128];           // x = x_drug @ drug_w
__device__ float g_Bcat1[128 * 576];      // [basis1 (8x64 cols) | root1 (64 cols)]
__device__ float g_xb1[NN * 576];         // x @ Bcat1
__device__ float g_agg1[NN * 64];
__device__ float g_h[NN * 64];            // layer-1 output (post relu)
__device__ float g_Bcat2[64 * 180];       // [basis2 (8x20 cols) | root2 (20 cols)]
__device__ float g_xb2[NN * 180];         // h @ Bcat2
__device__ float g_agg2[NN * 20];

// ---------------- zero the accumulators ----------------
__global__ void zero_all() {
    int stride = gridDim.x * blockDim.x;
    int i0 = blockIdx.x * blockDim.x + threadIdx.x;
    for (int i = i0; i < RR * NN; i += stride) g_deg[i] = 0;
    for (int i = i0; i < NN * 64; i += stride) g_agg1[i] = 0.0f;
    for (int i = i0; i < NN * 20; i += stride) g_agg2[i] = 0.0f;
}

// ---------------- degree count (shared by both layers) ----------------
__global__ void deg_kernel(const int* __restrict__ ei) {
    int idx = blockIdx.x * blockDim.x + threadIdx.x;
    if (idx >= NEDGE) return;
    int r = idx / EE;
    int e = idx - r * EE;
    int dst = ei[r * 2 * EE + EE + e];
    atomicAdd(&g_deg[r * NN + dst], 1);
}

// ---------------- build concatenated weight matrices ----------------
__global__ void build_b1(const float* __restrict__ basis1, const float* __restrict__ root1) {
    int idx = blockIdx.x * blockDim.x + threadIdx.x;
    if (idx >= 128 * 576) return;
    int i = idx / 576;
    int c = idx - i * 576;
    g_Bcat1[idx] = (c < 512) ? basis1[(c >> 6) * 128 * 64 + i * 64 + (c & 63)]
                             : root1[i * 64 + (c - 512)];
}

__global__ void build_b2(const float* __restrict__ basis2, const float* __restrict__ root2) {
    int idx = blockIdx.x * blockDim.x + threadIdx.x;
    if (idx >= 64 * 180) return;
    int i = idx / 180;
    int c = idx - i * 180;
    g_Bcat2[idx] = (c < 160) ? basis2[(c / 20) * 64 * 20 + i * 20 + (c % 20)]
                             : root2[i * 20 + (c - 160)];
}

// ---------------- generic fp32 tiled GEMM: C = A(MxK) @ B(KxN) ----------------
// BM=128, BN=64, BK=16, 256 threads, each thread 8x4 outputs.
// Requires K % 16 == 0 (true for 2048, 128, 64). M and N edges guarded.
__global__ void __launch_bounds__(256)
sgemm(const float* __restrict__ A, const float* __restrict__ B,
      float* __restrict__ C, int M, int N, int K) {
    __shared__ float As[128][16];
    __shared__ float Bs[16][64];

    const int m0 = blockIdx.y * 128;
    const int n0 = blockIdx.x * 64;
    const int tid = threadIdx.x;
    const int tx = tid & 15;        // 16 -> 64 cols (TN=4)
    const int ty = tid >> 4;        // 16 -> 128 rows (TM=8)

    const int a_row = tid >> 1;           // 0..127
    const int a_col = (tid & 1) * 8;      // 0 or 8
    const int b_row = tid >> 4;           // 0..15
    const int b_col = (tid & 15) * 4;     // 0..60

    float acc[8][4];
#pragma unroll
    for (int i = 0; i < 8; i++)
#pragma unroll
        for (int j = 0; j < 4; j++) acc[i][j] = 0.0f;

    for (int k0 = 0; k0 < K; k0 += 16) {
        // load A tile (rows guarded)
        if (m0 + a_row < M) {
            const float* ap = A + (size_t)(m0 + a_row) * K + k0 + a_col;
            float4 v0 = *(const float4*)(ap);
            float4 v1 = *(const float4*)(ap + 4);
            *(float4*)&As[a_row][a_col]     = v0;
            *(float4*)&As[a_row][a_col + 4] = v1;
        } else {
            float4 z = make_float4(0.f, 0.f, 0.f, 0.f);
            *(float4*)&As[a_row][a_col]     = z;
            *(float4*)&As[a_row][a_col + 4] = z;
        }
        // load B tile (cols guarded)
        if (n0 + b_col + 3 < N) {
            *(float4*)&Bs[b_row][b_col] =
                *(const float4*)(B + (size_t)(k0 + b_row) * N + n0 + b_col);
        } else {
#pragma unroll
            for (int j = 0; j < 4; j++)
                Bs[b_row][b_col + j] =
                    (n0 + b_col + j < N) ? B[(size_t)(k0 + b_row) * N + n0 + b_col + j] : 0.0f;
        }
        __syncthreads();

#pragma unroll
        for (int kk = 0; kk < 16; kk++) {
            float rB[4];
            *(float4*)rB = *(const float4*)&Bs[kk][tx * 4];
#pragma unroll
            for (int i = 0; i < 8; i++) {
                float a = As[ty * 8 + i][kk];
                acc[i][0] += a * rB[0];
                acc[i][1] += a * rB[1];
                acc[i][2] += a * rB[2];
                acc[i][3] += a * rB[3];
            }
        }
        __syncthreads();
    }

#pragma unroll
    for (int i = 0; i < 8; i++) {
        int m = m0 + ty * 8 + i;
        if (m >= M) continue;
#pragma unroll
        for (int j = 0; j < 4; j++) {
            int n = n0 + tx * 4 + j;
            if (n < N) C[(size_t)m * N + n] = acc[i][j];
        }
    }
}

// ---------------- edge pass layer 1: OUT=64, warp per edge ----------------
// agg1[dst,o] += (1/max(deg,1)) * sum_b comp1[r,b] * xb1[src, b*64+o]
__global__ void edge1_kernel(const int* __restrict__ ei, const float* __restrict__ comp) {
    int warp = (blockIdx.x * blockDim.x + threadIdx.x) >> 5;
    int lane = threadIdx.x & 31;
    if (warp >= NEDGE) return;
    int r = warp / EE;
    int e = warp - r * EE;
    const int* eir = ei + r * 2 * EE;
    int src = eir[e];
    int dst = eir[EE + e];
    float inv = 1.0f / (float)max(g_deg[r * NN + dst], 1);
    const float* cr = comp + r * 8;
    const float2* xr = (const float2*)(g_xb1 + (size_t)src * 576);

    float2 acc = make_float2(0.f, 0.f);
#pragma unroll
    for (int b = 0; b < 8; b++) {
        float c = __ldg(&cr[b]);
        float2 v = xr[b * 32 + lane];
        acc.x += c * v.x;
        acc.y += c * v.y;
    }
    float* ap = g_agg1 + (size_t)dst * 64 + lane * 2;
    atomicAdd(ap,     acc.x * inv);
    atomicAdd(ap + 1, acc.y * inv);
}

// ---------------- edge pass layer 2: OUT=20, warp per edge ----------------
__global__ void edge2_kernel(const int* __restrict__ ei, const float* __restrict__ comp) {
    int warp = (blockIdx.x * blockDim.x + threadIdx.x) >> 5;
    int lane = threadIdx.x & 31;
    if (warp >= NEDGE) return;
    int r = warp / EE;
    int e = warp - r * EE;
    const int* eir = ei + r * 2 * EE;
    int src = eir[e];
    int dst = eir[EE + e];
    float inv = 1.0f / (float)max(g_deg[r * NN + dst], 1);
    const float* cr = comp + r * 8;
    const float* xr = g_xb2 + (size_t)src * 180;

    float acc = 0.f;
#pragma unroll
    for (int b = 0; b < 8; b++) {
        float c = __ldg(&cr[b]);
        acc += c * xr[b * 20 + lane % 20];   // lanes >= 20 compute garbage, never stored
    }
    if (lane < 20) atomicAdd(&g_agg2[(size_t)dst * 20 + lane], acc * inv);
}

// ---------------- epilogues ----------------
__global__ void epi1_kernel(const float* __restrict__ bias1) {
    int idx = blockIdx.x * blockDim.x + threadIdx.x;
    if (idx >= NN * 64) return;
    int n = idx >> 6;
    int o = idx & 63;
    float v = g_agg1[idx] + g_xb1[(size_t)n * 576 + 512 + o] + bias1[o];
    g_h[idx] = v > 0.f ? v : 0.f;
}

__global__ void epi2_kernel(float* __restrict__ out, const float* __restrict__ bias2) {
    int idx = blockIdx.x * blockDim.x + threadIdx.x;
    if (idx >= NN * 20) return;
    int n = idx / 20;
    int o = idx - n * 20;
    out[idx] = g_agg2[idx] + g_xb2[(size_t)n * 180 + 160 + o] + bias2[o];
}

// ---------------- launch ----------------
extern "C" void kernel_launch(void* const* d_in, const int* in_sizes, int n_in,
                              void* d_out, int out_size) {
    const float* x_drug = (const float*)d_in[0];
    const float* drug_w = (const float*)d_in[1];
    const int*   ei     = (const int*)d_in[2];
    const float* basis1 = (const float*)d_in[3];
    const float* comp1  = (const float*)d_in[4];
    const float* root1  = (const float*)d_in[5];
    const float* bias1  = (const float*)d_in[6];
    const float* basis2 = (const float*)d_in[7];
    const float* comp2  = (const float*)d_in[8];
    const float* root2  = (const float*)d_in[9];
    const float* bias2  = (const float*)d_in[10];
    float* out = (float*)d_out;

    void *px, *pb1, *pxb1, *ph, *pb2, *pxb2;
    cudaGetSymbolAddress(&px,   g_x);
    cudaGetSymbolAddress(&pb1,  g_Bcat1);
    cudaGetSymbolAddress(&pxb1, g_xb1);
    cudaGetSymbolAddress(&ph,   g_h);
    cudaGetSymbolAddress(&pb2,  g_Bcat2);
    cudaGetSymbolAddress(&pxb2, g_xb2);

    zero_all<<<2048, 256>>>();
    deg_kernel<<<(NEDGE + 255) / 256, 256>>>(ei);
    build_b1<<<(128 * 576 + 255) / 256, 256>>>(basis1, root1);
    build_b2<<<(64 * 180 + 255) / 256, 256>>>(basis2, root2);

    // x = x_drug @ drug_w : (10000, 2048) @ (2048, 128)
    sgemm<<<dim3(2, 79), 256>>>(x_drug, drug_w, (float*)px, NN, 128, 2048);
    // xb1 = x @ [basis1|root1] : (10000, 128) @ (128, 576)
    sgemm<<<dim3(9, 79), 256>>>((const float*)px, (const float*)pb1, (float*)pxb1, NN, 576, 128);

    edge1_kernel<<<(NEDGE * 32 + 255) / 256, 256>>>(ei, comp1);
    epi1_kernel<<<(NN * 64 + 255) / 256, 256>>>(bias1);

    // xb2 = h @ [basis2|root2] : (10000, 64) @ (64, 180)
    sgemm<<<dim3(3, 79), 256>>>((const float*)ph, (const float*)pb2, (float*)pxb2, NN, 180, 64);

    edge2_kernel<<<(NEDGE * 32 + 255) / 256, 256>>>(ei, comp2);
    epi2_kernel<<<(NN * 20 + 255) / 256, 256>>>(out, bias2);
}

// round 2
// speedup vs baseline: 1.1752x; 1.1752x over previous
#include <cuda_runtime.h>

#define NN 10000
#define RR 100
#define EE 5000
#define NEDGE (RR * EE)

// ---------------- scratch (device globals; no allocations) ----------------
__device__ int   g_deg[RR * NN];          // edges per (relation, dst)
__device__ int   g_cnt[NN];               // total in-edges per dst (all relations)
__device__ int   g_off[NN + 1];           // CSR offsets
__device__ int   g_cur[NN];               // scatter cursors
__device__ int   g_rec[NEDGE];            // packed (r<<16)|src, grouped by dst
__device__ unsigned int g_ctr;            // dynamic tile counter for gemm1
__device__ float g_x[NN * 128];           // x = x_drug @ drug_w (split-K accumulated)
__device__ float g_Bcat1[128 * 576];      // [basis1 (8x64 cols) | root1 (64 cols)]
__device__ float g_xb1[NN * 576];         // x @ Bcat1
__device__ float g_h[NN * 64];            // layer-1 output (post relu)
__device__ float g_Bcat2[64 * 180];       // [basis2 (8x20 cols) | root2 (20 cols)]
__device__ float g_xb2[NN * 180];         // h @ Bcat2

// ---------------- zero pass ----------------
__global__ void zero_all() {
    int stride = gridDim.x * blockDim.x;
    int i0 = blockIdx.x * blockDim.x + threadIdx.x;
    for (int i = i0; i < RR * NN; i += stride) g_deg[i] = 0;
    for (int i = i0; i < NN; i += stride) g_cnt[i] = 0;
    for (int i = i0; i < NN * 128; i += stride) g_x[i] = 0.0f;
    if (i0 == 0) g_ctr = 0u;
}

// ---------------- degree + per-dst count ----------------
__global__ void deg_kernel(const int* __restrict__ ei) {
    int idx = blockIdx.x * blockDim.x + threadIdx.x;
    if (idx >= NEDGE) return;
    int r = idx / EE;
    int e = idx - r * EE;
    int dst = ei[r * 2 * EE + EE + e];
    atomicAdd(&g_deg[r * NN + dst], 1);
    atomicAdd(&g_cnt[dst], 1);
}

// ---------------- single-block exclusive scan over g_cnt -> g_off, g_cur ----------------
__global__ void scan_kernel() {
    __shared__ int sp[1024];
    int t = threadIdx.x;
    int base = t * 10;                       // 1024*10 >= 10000
    int loc[10];
    int s = 0;
#pragma unroll
    for (int j = 0; j < 10; j++) {
        int idx = base + j;
        int v = (idx < NN) ? g_cnt[idx] : 0;
        loc[j] = s;
        s += v;
    }
    sp[t] = s;
    __syncthreads();
    for (int off = 1; off < 1024; off <<= 1) {
        int v = (t >= off) ? sp[t - off] : 0;
        __syncthreads();
        sp[t] += v;
        __syncthreads();
    }
    int pre = (t > 0) ? sp[t - 1] : 0;
#pragma unroll
    for (int j = 0; j < 10; j++) {
        int idx = base + j;
        if (idx < NN) {
            int o = pre + loc[j];
            g_off[idx] = o;
            g_cur[idx] = o;
        }
    }
    if (t == 0) g_off[NN] = NEDGE;
}

// ---------------- scatter edges into dst buckets ----------------
__global__ void scatter_kernel(const int* __restrict__ ei) {
    int idx = blockIdx.x * blockDim.x + threadIdx.x;
    if (idx >= NEDGE) return;
    int r = idx / EE;
    int e = idx - r * EE;
    const int* eir = ei + r * 2 * EE;
    int src = eir[e];
    int dst = eir[EE + e];
    int pos = atomicAdd(&g_cur[dst], 1);
    g_rec[pos] = (r << 16) | src;
}

// ---------------- build concatenated weight matrices ----------------
__global__ void build_b1(const float* __restrict__ basis1, const float* __restrict__ root1) {
    int idx = blockIdx.x * blockDim.x + threadIdx.x;
    if (idx >= 128 * 576) return;
    int i = idx / 576;
    int c = idx - i * 576;
    g_Bcat1[idx] = (c < 512) ? basis1[(c >> 6) * 128 * 64 + i * 64 + (c & 63)]
                             : root1[i * 64 + (c - 512)];
}

__global__ void build_b2(const float* __restrict__ basis2, const float* __restrict__ root2) {
    int idx = blockIdx.x * blockDim.x + threadIdx.x;
    if (idx >= 64 * 180) return;
    int i = idx / 180;
    int c = idx - i * 180;
    g_Bcat2[idx] = (c < 160) ? basis2[(c / 20) * 64 * 20 + i * 20 + (c % 20)]
                             : root2[i * 20 + (c - 160)];
}

// ---------------- dynamic split-K persistent GEMM for GEMM1 ----------------
// C(10000x128) += A(10000x2048) @ B(2048x128), units of 128x64x256.
#define G1_MT 79      // ceil(10000/128)
#define G1_NT 2       // 128/64
#define G1_KT 8       // 2048/256
#define G1_UNITS (G1_MT * G1_NT * G1_KT)

__global__ void __launch_bounds__(256)
gemm1_dyn(const float* __restrict__ A, const float* __restrict__ B) {
    __shared__ float As[128][16];
    __shared__ float Bs[16][64];
    __shared__ int s_u;

    const int tid = threadIdx.x;
    const int tx = tid & 15;
    const int ty = tid >> 4;
    const int a_row = tid >> 1;
    const int a_col = (tid & 1) * 8;
    const int b_row = tid >> 4;
    const int b_col = (tid & 15) * 4;

    while (true) {
        __syncthreads();                 // protect s_u / smem from previous unit
        if (tid == 0) s_u = (int)atomicAdd(&g_ctr, 1u);
        __syncthreads();
        int u = s_u;
        if (u >= G1_UNITS) break;

        int kc = u & 7;
        int t2 = u >> 3;
        int n0 = (t2 & 1) * 64;
        int m0 = (t2 >> 1) * 128;
        int kbeg = kc * 256;

        float acc[8][4];
#pragma unroll
        for (int i = 0; i < 8; i++)
#pragma unroll
            for (int j = 0; j < 4; j++) acc[i][j] = 0.0f;

        for (int k0 = kbeg; k0 < kbeg + 256; k0 += 16) {
            if (m0 + a_row < NN) {
                const float* ap = A + (size_t)(m0 + a_row) * 2048 + k0 + a_col;
                *(float4*)&As[a_row][a_col]     = *(const float4*)(ap);
                *(float4*)&As[a_row][a_col + 4] = *(const float4*)(ap + 4);
            } else {
                float4 z = make_float4(0.f, 0.f, 0.f, 0.f);
                *(float4*)&As[a_row][a_col]     = z;
                *(float4*)&As[a_row][a_col + 4] = z;
            }
            *(float4*)&Bs[b_row][b_col] =
                *(const float4*)(B + (size_t)(k0 + b_row) * 128 + n0 + b_col);
            __syncthreads();

#pragma unroll
            for (int kk = 0; kk < 16; kk++) {
                float rB[4];
                *(float4*)rB = *(const float4*)&Bs[kk][tx * 4];
#pragma unroll
                for (int i = 0; i < 8; i++) {
                    float a = As[ty * 8 + i][kk];
                    acc[i][0] += a * rB[0];
                    acc[i][1] += a * rB[1];
                    acc[i][2] += a * rB[2];
                    acc[i][3] += a * rB[3];
                }
            }
            __syncthreads();
        }

#pragma unroll
        for (int i = 0; i < 8; i++) {
            int m = m0 + ty * 8 + i;
            if (m >= NN) continue;
            float* cp = g_x + (size_t)m * 128 + n0 + tx * 4;
#pragma unroll
            for (int j = 0; j < 4; j++) atomicAdd(cp + j, acc[i][j]);
        }
    }
}

// ---------------- generic fp32 tiled GEMM: C = A(MxK) @ B(KxN) ----------------
__global__ void __launch_bounds__(256)
sgemm(const float* __restrict__ A, const float* __restrict__ B,
      float* __restrict__ C, int M, int N, int K) {
    __shared__ float As[128][16];
    __shared__ float Bs[16][64];

    const int m0 = blockIdx.y * 128;
    const int n0 = blockIdx.x * 64;
    const int tid = threadIdx.x;
    const int tx = tid & 15;
    const int ty = tid >> 4;
    const int a_row = tid >> 1;
    const int a_col = (tid & 1) * 8;
    const int b_row = tid >> 4;
    const int b_col = (tid & 15) * 4;

    float acc[8][4];
#pragma unroll
    for (int i = 0; i < 8; i++)
#pragma unroll
        for (int j = 0; j < 4; j++) acc[i][j] = 0.0f;

    for (int k0 = 0; k0 < K; k0 += 16) {
        if (m0 + a_row < M) {
            const float* ap = A + (size_t)(m0 + a_row) * K + k0 + a_col;
            *(float4*)&As[a_row][a_col]     = *(const float4*)(ap);
            *(float4*)&As[a_row][a_col + 4] = *(const float4*)(ap + 4);
        } else {
            float4 z = make_float4(0.f, 0.f, 0.f, 0.f);
            *(float4*)&As[a_row][a_col]     = z;
            *(float4*)&As[a_row][a_col + 4] = z;
        }
        if (n0 + b_col + 3 < N) {
            *(float4*)&Bs[b_row][b_col] =
                *(const float4*)(B + (size_t)(k0 + b_row) * N + n0 + b_col);
        } else {
#pragma unroll
            for (int j = 0; j < 4; j++)
                Bs[b_row][b_col + j] =
                    (n0 + b_col + j < N) ? B[(size_t)(k0 + b_row) * N + n0 + b_col + j] : 0.0f;
        }
        __syncthreads();

#pragma unroll
        for (int kk = 0; kk < 16; kk++) {
            float rB[4];
            *(float4*)rB = *(const float4*)&Bs[kk][tx * 4];
#pragma unroll
            for (int i = 0; i < 8; i++) {
                float a = As[ty * 8 + i][kk];
                acc[i][0] += a * rB[0];
                acc[i][1] += a * rB[1];
                acc[i][2] += a * rB[2];
                acc[i][3] += a * rB[3];
            }
        }
        __syncthreads();
    }

#pragma unroll
    for (int i = 0; i < 8; i++) {
        int m = m0 + ty * 8 + i;
        if (m >= M) continue;
#pragma unroll
        for (int j = 0; j < 4; j++) {
            int n = n0 + tx * 4 + j;
            if (n < N) C[(size_t)m * N + n] = acc[i][j];
        }
    }
}

// ---------------- layer-1 aggregation: warp per dst, no atomics, fused epilogue ----------------
__global__ void agg1_kernel(const float* __restrict__ comp, const float* __restrict__ bias) {
    int w = (blockIdx.x * blockDim.x + threadIdx.x) >> 5;
    int lane = threadIdx.x & 31;
    if (w >= NN) return;
    int beg = g_off[w];
    int end = g_off[w + 1];

    float ax = 0.f, ay = 0.f;
    for (int i = beg; i < end; i++) {
        int rec = g_rec[i];
        int src = rec & 0xFFFF;
        int r = rec >> 16;
        float inv = 1.0f / (float)max(g_deg[r * NN + w], 1);
        float4 c0 = *(const float4*)(comp + r * 8);
        float4 c1 = *(const float4*)(comp + r * 8 + 4);
        const float2* xr = (const float2*)(g_xb1 + (size_t)src * 576);
        float mx = 0.f, my = 0.f;
        float2 v;
        v = xr[0 * 32 + lane]; mx += c0.x * v.x; my += c0.x * v.y;
        v = xr[1 * 32 + lane]; mx += c0.y * v.x; my += c0.y * v.y;
        v = xr[2 * 32 + lane]; mx += c0.z * v.x; my += c0.z * v.y;
        v = xr[3 * 32 + lane]; mx += c0.w * v.x; my += c0.w * v.y;
        v = xr[4 * 32 + lane]; mx += c1.x * v.x; my += c1.x * v.y;
        v = xr[5 * 32 + lane]; mx += c1.y * v.x; my += c1.y * v.y;
        v = xr[6 * 32 + lane]; mx += c1.z * v.x; my += c1.z * v.y;
        v = xr[7 * 32 + lane]; mx += c1.w * v.x; my += c1.w * v.y;
        ax += inv * mx;
        ay += inv * my;
    }
    int o = lane * 2;
    const float* rootrow = g_xb1 + (size_t)w * 576 + 512;
    float r0 = ax + rootrow[o]     + bias[o];
    float r1 = ay + rootrow[o + 1] + bias[o + 1];
    g_h[w * 64 + o]     = fmaxf(r0, 0.f);
    g_h[w * 64 + o + 1] = fmaxf(r1, 0.f);
}

// ---------------- layer-2 aggregation: warp per dst, fused epilogue ----------------
__global__ void agg2_kernel(const float* __restrict__ comp, const float* __restrict__ bias,
                            float* __restrict__ out) {
    int w = (blockIdx.x * blockDim.x + threadIdx.x) >> 5;
    int lane = threadIdx.x & 31;
    if (w >= NN) return;
    int beg = g_off[w];
    int end = g_off[w + 1];
    int l = (lane < 20) ? lane : 0;   // safe index for inactive lanes

    float acc = 0.f;
    for (int i = beg; i < end; i++) {
        int rec = g_rec[i];
        int src = rec & 0xFFFF;
        int r = rec >> 16;
        float inv = 1.0f / (float)max(g_deg[r * NN + w], 1);
        float4 c0 = *(const float4*)(comp + r * 8);
        float4 c1 = *(const float4*)(comp + r * 8 + 4);
        const float* xr = g_xb2 + (size_t)src * 180;
        float m = 0.f;
        m += c0.x * xr[0 * 20 + l];
        m += c0.y * xr[1 * 20 + l];
        m += c0.z * xr[2 * 20 + l];
        m += c0.w * xr[3 * 20 + l];
        m += c1.x * xr[4 * 20 + l];
        m += c1.y * xr[5 * 20 + l];
        m += c1.z * xr[6 * 20 + l];
        m += c1.w * xr[7 * 20 + l];
        acc += inv * m;
    }
    if (lane < 20) {
        out[w * 20 + lane] = acc + g_xb2[(size_t)w * 180 + 160 + lane] + bias[lane];
    }
}

// ---------------- launch ----------------
extern "C" void kernel_launch(void* const* d_in, const int* in_sizes, int n_in,
                              void* d_out, int out_size) {
    const float* x_drug = (const float*)d_in[0];
    const float* drug_w = (const float*)d_in[1];
    const int*   ei     = (const int*)d_in[2];
    const float* basis1 = (const float*)d_in[3];
    const float* comp1  = (const float*)d_in[4];
    const float* root1  = (const float*)d_in[5];
    const float* bias1  = (const float*)d_in[6];
    const float* basis2 = (const float*)d_in[7];
    const float* comp2  = (const float*)d_in[8];
    const float* root2  = (const float*)d_in[9];
    const float* bias2  = (const float*)d_in[10];
    float* out = (float*)d_out;

    void *px, *pb1, *pxb1, *ph, *pb2, *pxb2;
    cudaGetSymbolAddress(&px,   g_x);
    cudaGetSymbolAddress(&pb1,  g_Bcat1);
    cudaGetSymbolAddress(&pxb1, g_xb1);
    cudaGetSymbolAddress(&ph,   g_h);
    cudaGetSymbolAddress(&pb2,  g_Bcat2);
    cudaGetSymbolAddress(&pxb2, g_xb2);

    zero_all<<<1024, 256>>>();
    deg_kernel<<<(NEDGE + 255) / 256, 256>>>(ei);
    scan_kernel<<<1, 1024>>>();
    scatter_kernel<<<(NEDGE + 255) / 256, 256>>>(ei);
    build_b1<<<(128 * 576 + 255) / 256, 256>>>(basis1, root1);
    build_b2<<<(64 * 180 + 255) / 256, 256>>>(basis2, root2);

    // x = x_drug @ drug_w : (10000, 2048) @ (2048, 128), dynamic split-K
    gemm1_dyn<<<296, 256>>>(x_drug, drug_w);
    // xb1 = x @ [basis1|root1] : (10000, 128) @ (128, 576)
    sgemm<<<dim3(9, 79), 256>>>((const float*)px, (const float*)pb1, (float*)pxb1, NN, 576, 128);

    agg1_kernel<<<(NN * 32 + 255) / 256, 256>>>(comp1, bias1);

    // xb2 = h @ [basis2|root2] : (10000, 64) @ (64, 180)
    sgemm<<<dim3(3, 79), 256>>>((const float*)ph, (const float*)pb2, (float*)pxb2, NN, 180, 64);

    agg2_kernel<<<(NN * 32 + 255) / 256, 256>>>(comp2, bias2, out);
}